// round 16
// baseline (speedup 1.0000x reference)
#include <cuda_runtime.h>
#include <cuda_fp16.h>
#include <math.h>
#include <stdint.h>

#define NPTS 16384
#define KNB  16
#define ASTR 40    // smem row stride (halfs) for K32-staged GEMM cores
#define ASTR2 136  // smem row stride (halfs) for 128-wide tiles in fused gemm2

// ---------------- device scratch (static: no allocations allowed) ----------------
__device__ int   d_knn32[NPTS * KNB];
__device__ int   d_knn_bad;                  // 0 => int64 knn, nonzero => int32
__device__ float d_C0[(size_t)NPTS * 512];
__device__ float d_fa[(size_t)NPTS * 512];
__device__ float d_fb[(size_t)NPTS * 512];
__device__ float d_r[(size_t)NPTS * 512];    // f @ w_res^T
__device__ float d_dv[512];
__device__ float d_bsum[512];

// fp16 planes (activations single-plane; ALL weights single-plane)
__device__ __half d_G1f[NPTS * 128];
__device__ __half d_x1f[NPTS * 128];
__device__ __half d_ax1f[NPTS * 128];
__device__ __half d_Gcf[(size_t)NPTS * 384];
__device__ __half d_faf[(size_t)NPTS * 512];
__device__ __half d_fbf[(size_t)NPTS * 512];
__device__ __half d_w2h[512 * 512];
__device__ __half d_wch[640 * 512];                 // [w_mlp1 ; w_res]

// ---------------- knn dtype detection + convert ----------------
__global__ void k_detect(const void* __restrict__ knn) {
    const long long* p = (const long long*)knn;
    const int total = NPTS * KNB / 2;
    int local = 0;
    for (int i = blockIdx.x * blockDim.x + threadIdx.x; i < total; i += gridDim.x * blockDim.x) {
        long long v = p[i];
        if (v < 0 || v >= NPTS) local = 1;
    }
    if (local) atomicOr(&d_knn_bad, 1);
}

__global__ void k_cvt(const void* __restrict__ knn) {
    int i = blockIdx.x * blockDim.x + threadIdx.x;
    if (i >= NPTS * KNB) return;
    if (d_knn_bad)
        d_knn32[i] = ((const int*)knn)[i];
    else
        d_knn32[i] = (int)((const long long*)knn)[i];
}

// ---------------- weight planes (hi only) ----------------
__global__ void k_wcvt(const float* __restrict__ w_mlp2, const float* __restrict__ w_mlp1,
                       const float* __restrict__ w_res) {
    int i = blockIdx.x * blockDim.x + threadIdx.x;
    if (i >= 640 * 512) return;
    if (i < 512 * 512) d_w2h[i] = __float2half_rn(w_mlp2[i]);
    float v = (i < 128 * 512) ? w_mlp1[i] : w_res[i - 128 * 512];
    d_wch[i] = __float2half_rn(v);
}

// ---------------- fused: geo mean + tiny geo linears + vec tail ----------------
__global__ void __launch_bounds__(256) k_prepsm(
        const float* __restrict__ inp,
        const float* __restrict__ w_lfa1, const float* __restrict__ b_lfa1,
        const float* __restrict__ w_lfa2, const float* __restrict__ b_lfa2,
        const float* __restrict__ w_mlp2, const float* __restrict__ b_mlp1,
        const float* __restrict__ b_mlp2, const float* __restrict__ b_res) {
    int tid = threadIdx.x;
    if (blockIdx.x == 256) {
        int j = tid * 2;
        if (j < 512) {
#pragma unroll
            for (int t = 0; t < 2; t++) {
                int jj = j + t;
                d_bsum[jj] = b_mlp2[jj] + b_res[jj];
                float s = 0.f;
#pragma unroll 8
                for (int c = 0; c < 128; c++) s += w_mlp2[jj * 512 + 384 + c] * b_mlp1[c];
                d_dv[jj] = s;
            }
        }
        return;
    }
    __shared__ float s_w2[256 * 4], s_b2[256], s_w1[128 * 4], s_b1[128];
    __shared__ float s_geo[64 * 4];
    for (int i = tid; i < 1024; i += 256) s_w2[i] = w_lfa2[i];
    for (int i = tid; i < 512;  i += 256) s_w1[i] = w_lfa1[i];
    for (int i = tid; i < 256;  i += 256) s_b2[i] = b_lfa2[i];
    if (tid < 128) s_b1[tid] = b_lfa1[tid];
    if (tid < 64) {
        int n = blockIdx.x * 64 + tid;
        float xi = inp[3 * n + 0], yi = inp[3 * n + 1], zi = inp[3 * n + 2];
        float sx = 0.f, sy = 0.f, sz = 0.f, sn = 0.f;
#pragma unroll
        for (int k = 0; k < KNB; k++) {
            int j = d_knn32[n * KNB + k];
            float dx = xi - inp[3 * j + 0];
            float dy = yi - inp[3 * j + 1];
            float dz = zi - inp[3 * j + 2];
            sx += dx; sy += dy; sz += dz;
            sn += sqrtf(dx * dx + dy * dy + dz * dz);
        }
        const float s = 1.0f / KNB;
        s_geo[tid * 4 + 0] = sx * s;
        s_geo[tid * 4 + 1] = sy * s;
        s_geo[tid * 4 + 2] = sz * s;
        s_geo[tid * 4 + 3] = sn * s;
    }
    __syncthreads();
    int wid = tid >> 5, lane = tid & 31;
#pragma unroll 1
    for (int p = 0; p < 8; p++) {
        int nl = wid * 8 + p;
        int n = blockIdx.x * 64 + nl;
        float4 g = *(const float4*)(s_geo + nl * 4);
#pragma unroll
        for (int t = 0; t < 2; t++) {
            int j0 = t * 128 + lane * 4;
            float r[4];
#pragma unroll
            for (int u = 0; u < 4; u++) {
                int j = j0 + u;
                r[u] = s_b2[j] + g.x * s_w2[j * 4 + 0] + g.y * s_w2[j * 4 + 1]
                               + g.z * s_w2[j * 4 + 2] + g.w * s_w2[j * 4 + 3];
            }
            size_t o = (size_t)n * 384 + j0;
            *(__half2*)(d_Gcf + o)     = __floats2half2_rn(r[0], r[1]);
            *(__half2*)(d_Gcf + o + 2) = __floats2half2_rn(r[2], r[3]);
        }
        {
            int j0 = lane * 4;
            float r[4];
#pragma unroll
            for (int u = 0; u < 4; u++) {
                int j = j0 + u;
                r[u] = s_b1[j] + g.x * s_w1[j * 4 + 0] + g.y * s_w1[j * 4 + 1]
                               + g.z * s_w1[j * 4 + 2] + g.w * s_w1[j * 4 + 3];
            }
            size_t o = (size_t)n * 128 + j0;
            *(__half2*)(d_G1f + o)     = __floats2half2_rn(r[0], r[1]);
            *(__half2*)(d_G1f + o + 2) = __floats2half2_rn(r[2], r[3]);
        }
    }
}

// ---------------- gather-mean kernels (one warp per point, fp16 rows) ----------------
__global__ void __launch_bounds__(256) k_gather0() {
    int t = blockIdx.x * blockDim.x + threadIdx.x;
    int n = t >> 5; if (n >= NPTS) return;
    int lane = t & 31;
    const int* kn = d_knn32 + n * KNB;
    float a0 = 0.f, a1 = 0.f, a2 = 0.f, a3 = 0.f;
#pragma unroll
    for (int k = 0; k < KNB; k++) {
        uint2 v = *(const uint2*)(d_G1f + (size_t)kn[k] * 128 + lane * 4);
        __half2 p0 = *(__half2*)&v.x, p1 = *(__half2*)&v.y;
        a0 += __low2float(p0); a1 += __high2float(p0);
        a2 += __low2float(p1); a3 += __high2float(p1);
    }
    const float s = 1.0f / KNB;
    size_t o = (size_t)n * 384 + 256 + lane * 4;
    *(__half2*)(d_Gcf + o)     = __floats2half2_rn(a0 * s, a1 * s);
    *(__half2*)(d_Gcf + o + 2) = __floats2half2_rn(a2 * s, a3 * s);
}

__global__ void __launch_bounds__(256) k_gather1() {
    int t = blockIdx.x * blockDim.x + threadIdx.x;
    int n = t >> 5; if (n >= NPTS) return;
    int lane = t & 31;
    const int* kn = d_knn32 + n * KNB;
    float a0 = 0.f, a1 = 0.f, a2 = 0.f, a3 = 0.f;
#pragma unroll
    for (int k = 0; k < KNB; k++) {
        uint2 v = *(const uint2*)(d_x1f + (size_t)kn[k] * 128 + lane * 4);
        __half2 p0 = *(__half2*)&v.x, p1 = *(__half2*)&v.y;
        a0 += __low2float(p0); a1 += __high2float(p0);
        a2 += __low2float(p1); a3 += __high2float(p1);
    }
    const float s = 1.0f / KNB;
    uint2 o;
    *(__half2*)&o.x = __floats2half2_rn(a0 * s, a1 * s);
    *(__half2*)&o.y = __floats2half2_rn(a2 * s, a3 * s);
    *(uint2*)(d_ax1f + (size_t)n * 128 + lane * 4) = o;
}

// ================= fp16 tensor-core GEMM core (HMMA + ldmatrix, single-plane) =================
__device__ __forceinline__ void mma16816(float* c, const unsigned* a, unsigned b0, unsigned b1) {
    asm volatile(
        "mma.sync.aligned.m16n8k16.row.col.f32.f16.f16.f32 "
        "{%0,%1,%2,%3}, {%4,%5,%6,%7}, {%8,%9}, {%0,%1,%2,%3};"
        : "+f"(c[0]), "+f"(c[1]), "+f"(c[2]), "+f"(c[3])
        : "r"(a[0]), "r"(a[1]), "r"(a[2]), "r"(a[3]), "r"(b0), "r"(b1));
}

#define LDMX4(d, addr) \
    asm volatile("ldmatrix.sync.aligned.m8n8.x4.shared.b16 {%0,%1,%2,%3}, [%4];" \
        : "=r"((d)[0]), "=r"((d)[1]), "=r"((d)[2]), "=r"((d)[3]) : "r"(addr))

__device__ __forceinline__ void cp16(__half* s, const __half* g) {
    unsigned sa = (unsigned)__cvta_generic_to_shared(s);
    asm volatile("cp.async.cg.shared.global [%0], [%1], 16;" :: "r"(sa), "l"(g));
}

#define PLANE (128 * ASTR)
#define GEMM_SMEM1  (2 * 2 * PLANE * 2)           // 40960 B
#define GEMM2F_SMEM (2 * 128 * ASTR2 * 2)         // 69632 B (A tile + B tile)

#define LANE_OFFS(S) \
    const int a_off = (warp_m * 32 + ((lane >> 3) & 1) * 8 + (lane & 7)) * (S) \
                      + ((lane >> 4) * 8); \
    const int b_off = (warp_n * 64 + ((lane >> 4) & 1) * 8 + (lane & 7)) * (S) \
                      + (((lane >> 3) & 1) * 8);

__device__ __forceinline__ void ld_stage1(__half* s,
        const __half* A, int lda, const __half* Bh, int ldb, int k0, int tid) {
#pragma unroll
    for (int i = 0; i < 2; i++) {
        int chunk = tid + i * 256;
        int r = chunk >> 2, c8 = (chunk & 3) * 8;
        cp16(s + 0 * PLANE + r * ASTR + c8, A  + (size_t)r * lda + k0 + c8);
        cp16(s + 1 * PLANE + r * ASTR + c8, Bh + (size_t)r * ldb + k0 + c8);
    }
}

__device__ __forceinline__ void gemm_mma1(
        const __half* __restrict__ A, int lda,
        const __half* __restrict__ Bh, int ldb,
        int K, float (&acc)[2][8][4]) {
    extern __shared__ __half smdyn[];
    const int tid = threadIdx.x;
    const int lane = tid & 31, wid = tid >> 5;
    const int warp_m = wid & 3, warp_n = wid >> 2;
    const int nk = K / 32;
    const unsigned smbase = (unsigned)__cvta_generic_to_shared(smdyn);
    LANE_OFFS(ASTR);

    ld_stage1(smdyn, A, lda, Bh, ldb, 0, tid);
    asm volatile("cp.async.commit_group;");
    for (int t = 0; t < nk; t++) {
        int st = t & 1;
        if (t + 1 < nk) {
            ld_stage1(smdyn + (st ^ 1) * 2 * PLANE, A, lda, Bh, ldb, (t + 1) * 32, tid);
            asm volatile("cp.async.commit_group;");
            asm volatile("cp.async.wait_group 1;");
        } else {
            asm volatile("cp.async.wait_group 0;");
        }
        __syncthreads();
        const unsigned aB  = smbase + (st * 2 * PLANE) * 2;
        const unsigned bhB = aB + PLANE * 2;
#pragma unroll
        for (int ks = 0; ks < 32; ks += 16) {
            unsigned af[2][4];
            LDMX4(af[0], aB + (unsigned)(a_off + ks) * 2);
            LDMX4(af[1], aB + (unsigned)(a_off + 16 * ASTR + ks) * 2);
#pragma unroll
            for (int p = 0; p < 4; p++) {
                unsigned bh[4];
                unsigned bo = (unsigned)(b_off + p * 16 * ASTR + ks) * 2;
                LDMX4(bh, bhB + bo);
                mma16816(acc[0][2 * p],     af[0], bh[0], bh[1]);
                mma16816(acc[1][2 * p],     af[1], bh[0], bh[1]);
                mma16816(acc[0][2 * p + 1], af[0], bh[2], bh[3]);
                mma16816(acc[1][2 * p + 1], af[1], bh[2], bh[3]);
            }
        }
        __syncthreads();
    }
}

#define EPILOG_COORDS() \
    const int lane = threadIdx.x & 31, wid = threadIdx.x >> 5; \
    const int warp_m = wid & 3, warp_n = wid >> 2; \
    const int grp4 = lane >> 2, tig = lane & 3;

// ---------------- GEMM C0: Gcf @ W2[:, :384]^T + bsum ; fa = C0 + dv (+ fp16 plane) ----------------
__global__ void __launch_bounds__(256, 2) k_gemmC0() {
    float acc[2][8][4] = {};
    gemm_mma1(d_Gcf + (size_t)blockIdx.x * 128 * 384, 384,
              d_w2h + (size_t)blockIdx.y * 128 * 512, 512, 384, acc);
    EPILOG_COORDS();
#pragma unroll
    for (int mi = 0; mi < 2; mi++) {
#pragma unroll
        for (int ni = 0; ni < 8; ni++) {
            int r0 = blockIdx.x * 128 + warp_m * 32 + mi * 16 + grp4;
            int cc = blockIdx.y * 128 + warp_n * 64 + ni * 8 + tig * 2;
            float2 bs = *(const float2*)(d_bsum + cc);
            float2 dv = *(const float2*)(d_dv + cc);
            float* a = acc[mi][ni];
#pragma unroll
            for (int h2 = 0; h2 < 2; h2++) {
                int r = r0 + h2 * 8;
                size_t o = (size_t)r * 512 + cc;
                float c0 = a[2 * h2 + 0] + bs.x, c1 = a[2 * h2 + 1] + bs.y;
                *(float2*)(d_C0 + o) = make_float2(c0, c1);
                float f0 = c0 + dv.x, f1 = c1 + dv.y;
                *(float2*)(d_fa + o) = make_float2(f0, f1);
                *(__half2*)(d_faf + o) = __floats2half2_rn(f0, f1);
            }
        }
    }
}

// ---------------- GEMM1a: x1 = f @ w_mlp1^T + b  (N=128) ----------------
__global__ void __launch_bounds__(256, 2) k_gemm1a(int fsel, const float* __restrict__ b_mlp1) {
    const __half* Af = (fsel ? d_fbf : d_faf) + (size_t)blockIdx.x * 128 * 512;
    float acc[2][8][4] = {};
    gemm_mma1(Af, 512, d_wch, 512, 512, acc);
    EPILOG_COORDS();
#pragma unroll
    for (int mi = 0; mi < 2; mi++) {
#pragma unroll
        for (int ni = 0; ni < 8; ni++) {
            int r0 = blockIdx.x * 128 + warp_m * 32 + mi * 16 + grp4;
            int cl = warp_n * 64 + ni * 8 + tig * 2;
            float2 bs = *(const float2*)(b_mlp1 + cl);
            float* a = acc[mi][ni];
#pragma unroll
            for (int h2 = 0; h2 < 2; h2++) {
                int r = r0 + h2 * 8;
                *(__half2*)(d_x1f + (size_t)r * 128 + cl) =
                    __floats2half2_rn(a[2 * h2 + 0] + bs.x, a[2 * h2 + 1] + bs.y);
            }
        }
    }
}

// ---------------- GEMM1b: r = f @ w_res^T  (N=512) ----------------
__global__ void __launch_bounds__(256, 2) k_gemm1b(int fsel) {
    const __half* Af = (fsel ? d_fbf : d_faf) + (size_t)blockIdx.x * 128 * 512;
    const __half* Bh = d_wch + (size_t)(blockIdx.y + 1) * 128 * 512;   // w_res rows
    float acc[2][8][4] = {};
    gemm_mma1(Af, 512, Bh, 512, 512, acc);
    EPILOG_COORDS();
#pragma unroll
    for (int mi = 0; mi < 2; mi++) {
#pragma unroll
        for (int ni = 0; ni < 8; ni++) {
            int r0 = blockIdx.x * 128 + warp_m * 32 + mi * 16 + grp4;
            int cc = blockIdx.y * 128 + warp_n * 64 + ni * 8 + tig * 2;
            float* a = acc[mi][ni];
#pragma unroll
            for (int h2 = 0; h2 < 2; h2++) {
                int r = r0 + h2 * 8;
                *(float2*)(d_r + (size_t)r * 512 + cc) =
                    make_float2(a[2 * h2 + 0], a[2 * h2 + 1]);
            }
        }
    }
}

// ---------------- GEMM2 fused: gather aax in-kernel, then f_new = C0+f+r+aax@W2r^T ----------------
__global__ void __launch_bounds__(256, 2) k_gemm2f(int fsel, int dsel, float* __restrict__ outp) {
    extern __shared__ __half smdyn[];
    __half* sA = smdyn;                       // 128 x ASTR2 (aax tile, K=128)
    __half* sB = smdyn + 128 * ASTR2;         // 128 x ASTR2 (weight chunk)
    const float* f = fsel ? d_fb : d_fa;
    float* dst = (dsel == 0) ? d_fb : (dsel == 1) ? d_fa : outp;
    __half* dstf = (dsel == 0) ? d_fbf : d_faf;
    const int tid = threadIdx.x;
    const int lane = tid & 31, wid = tid >> 5;
    const int warp_m = wid & 3, warp_n = wid >> 2;
    const int row0 = blockIdx.x * 128;

    // phase 1: gather this block's aax rows (identical arithmetic to old k_gather2)
#pragma unroll 1
    for (int rr = 0; rr < 16; rr++) {
        int rloc = wid * 16 + rr;
        const int* kn = d_knn32 + (row0 + rloc) * KNB;
        float a0 = 0.f, a1 = 0.f, a2 = 0.f, a3 = 0.f;
#pragma unroll
        for (int k = 0; k < KNB; k++) {
            uint2 v = *(const uint2*)(d_ax1f + (size_t)kn[k] * 128 + lane * 4);
            __half2 p0 = *(__half2*)&v.x, p1 = *(__half2*)&v.y;
            a0 += __low2float(p0); a1 += __high2float(p0);
            a2 += __low2float(p1); a3 += __high2float(p1);
        }
        const float s = 1.0f / KNB;
        *(__half2*)(sA + rloc * ASTR2 + lane * 4)     = __floats2half2_rn(a0 * s, a1 * s);
        *(__half2*)(sA + rloc * ASTR2 + lane * 4 + 2) = __floats2half2_rn(a2 * s, a3 * s);
    }
    __syncthreads();

    LANE_OFFS(ASTR2);
    const unsigned sAb = (unsigned)__cvta_generic_to_shared(sA);
    const unsigned sBb = (unsigned)__cvta_generic_to_shared(sB);
    const int grp4 = lane >> 2, tig = lane & 3;

#pragma unroll 1
    for (int nc = 0; nc < 4; nc++) {
        // load weight chunk: rows nc*128..+127 of d_w2h, cols 384..512 (K=128)
        // 128 rows x 128 halfs = 2048 x 16B copies: 8 iters x 256 threads
#pragma unroll
        for (int i = 0; i < 8; i++) {
            int chunk = tid + i * 256;            // 0..2047
            int r = chunk >> 4, c8 = (chunk & 15) * 8;
            cp16(sB + r * ASTR2 + c8,
                 d_w2h + (size_t)(nc * 128 + r) * 512 + 384 + c8);
        }
        asm volatile("cp.async.commit_group;");
        asm volatile("cp.async.wait_group 0;");
        __syncthreads();

        float acc[2][8][4] = {};
#pragma unroll
        for (int ks = 0; ks < 128; ks += 16) {
            unsigned af[2][4];
            LDMX4(af[0], sAb + (unsigned)(a_off + ks) * 2);
            LDMX4(af[1], sAb + (unsigned)(a_off + 16 * ASTR2 + ks) * 2);
#pragma unroll
            for (int p = 0; p < 4; p++) {
                unsigned bh[4];
                unsigned bo = (unsigned)(b_off + p * 16 * ASTR2 + ks) * 2;
                LDMX4(bh, sBb + bo);
                mma16816(acc[0][2 * p],     af[0], bh[0], bh[1]);
                mma16816(acc[1][2 * p],     af[1], bh[0], bh[1]);
                mma16816(acc[0][2 * p + 1], af[0], bh[2], bh[3]);
                mma16816(acc[1][2 * p + 1], af[1], bh[2], bh[3]);
            }
        }
        // epilogue for this N-chunk
#pragma unroll
        for (int mi = 0; mi < 2; mi++) {
#pragma unroll
            for (int ni = 0; ni < 8; ni++) {
                int r0 = row0 + warp_m * 32 + mi * 16 + grp4;
                int cc = nc * 128 + warp_n * 64 + ni * 8 + tig * 2;
                float* a = acc[mi][ni];
#pragma unroll
                for (int h2 = 0; h2 < 2; h2++) {
                    int r = r0 + h2 * 8;
                    size_t o = (size_t)r * 512 + cc;
                    float2 c0 = *(const float2*)(d_C0 + o);
                    float2 fv = *(const float2*)(f + o);
                    float2 rv = *(const float2*)(d_r + o);
                    float v0 = a[2 * h2 + 0] + c0.x + fv.x + rv.x;
                    float v1 = a[2 * h2 + 1] + c0.y + fv.y + rv.y;
                    *(float2*)(dst + o) = make_float2(v0, v1);
                    if (dsel != 2)
                        *(__half2*)(dstf + o) = __floats2half2_rn(v0, v1);
                }
            }
        }
        __syncthreads();
    }
}

// ---------------- launch ----------------
extern "C" void kernel_launch(void* const* d_in, const int* in_sizes, int n_in,
                              void* d_out, int out_size) {
    const float* inputs = (const float*)d_in[0];
    const void*  knn    = d_in[1];
    const float* w_mlp1 = (const float*)d_in[2];
    const float* b_mlp1 = (const float*)d_in[3];
    const float* w_lfa1 = (const float*)d_in[4];
    const float* b_lfa1 = (const float*)d_in[5];
    const float* w_lfa2 = (const float*)d_in[6];
    const float* b_lfa2 = (const float*)d_in[7];
    const float* w_mlp2 = (const float*)d_in[8];
    const float* b_mlp2 = (const float*)d_in[9];
    const float* w_res  = (const float*)d_in[10];
    const float* b_res  = (const float*)d_in[11];
    float* out = (float*)d_out;

    static int init_done = 0;
    static cudaStream_t s1;
    static cudaEvent_t ev_fork, ev_join;
    if (!init_done) {
        cudaFuncSetAttribute(k_gemmC0, cudaFuncAttributeMaxDynamicSharedMemorySize, GEMM_SMEM1);
        cudaFuncSetAttribute(k_gemm1a, cudaFuncAttributeMaxDynamicSharedMemorySize, GEMM_SMEM1);
        cudaFuncSetAttribute(k_gemm1b, cudaFuncAttributeMaxDynamicSharedMemorySize, GEMM_SMEM1);
        cudaFuncSetAttribute(k_gemm2f, cudaFuncAttributeMaxDynamicSharedMemorySize, GEMM2F_SMEM);
        cudaStreamCreateWithFlags(&s1, cudaStreamNonBlocking);
        cudaEventCreateWithFlags(&ev_fork, cudaEventDisableTiming);
        cudaEventCreateWithFlags(&ev_join, cudaEventDisableTiming);
        init_done = 1;
    }

    // ---- prologue: weight conversion overlapped with knn/geo chain ----
    cudaEventRecord(ev_fork, 0);
    cudaStreamWaitEvent(s1, ev_fork, 0);
    k_wcvt<<<(640 * 512) / 256, 256, 0, s1>>>(w_mlp2, w_mlp1, w_res);
    cudaEventRecord(ev_join, s1);

    k_detect<<<128, 256>>>(knn);
    k_cvt<<<(NPTS * KNB) / 256, 256>>>(knn);
    k_prepsm<<<257, 256>>>(inputs, w_lfa1, b_lfa1, w_lfa2, b_lfa2,
                           w_mlp2, b_mlp1, b_mlp2, b_res);
    k_gather0<<<(NPTS * 32) / 256, 256>>>();
    cudaStreamWaitEvent(0, ev_join, 0);
    k_gemmC0<<<dim3(128, 4), 256, GEMM_SMEM1>>>();

    int fsel = 0;
    for (int it = 0; it < 3; it++) {
        // fork: gemm1b (needs only f) beside gemm1a -> gather1
        cudaEventRecord(ev_fork, 0);
        cudaStreamWaitEvent(s1, ev_fork, 0);
        k_gemm1b<<<dim3(128, 4), 256, GEMM_SMEM1, s1>>>(fsel);
        cudaEventRecord(ev_join, s1);

        k_gemm1a<<<dim3(128, 1), 256, GEMM_SMEM1>>>(fsel, b_mlp1);
        k_gather1<<<(NPTS * 32) / 256, 256>>>();

        cudaStreamWaitEvent(0, ev_join, 0);
        int dsel = (it == 2) ? 2 : (fsel == 0 ? 0 : 1);
        k_gemm2f<<<128, 256, GEMM2F_SMEM>>>(fsel, dsel, out);
        fsel ^= 1;
    }
    (void)in_sizes; (void)n_in; (void)out_size;
}